// round 10
// baseline (speedup 1.0000x reference)
#include <cuda_runtime.h>
#include <cuda_fp16.h>
#include <cstdint>

#define NN 50000
#define EE 800000
#define IND 16
#define HD 128
#define WW 256          // fused width (policy 0..127, value 128..255)
#define TILE 32         // nodes per block in gemm2f
#define GP 36           // padded smem row (floats) for transposed tile
#define SCB 49          // scan blocks

// ---------------- device scratch (static, no allocation; zero-initialized) ----
__device__ int    g_cnt[NN + 16];
__device__ int    g_cur[NN];
__device__ int    g_off[NN + 1];
__device__ int    g_bsum[64];
__device__ int2   g_edge[EE + NN];             // (src, norm-bits) per CSR slot
__device__ float  g_dis[NN];
__device__ __half g_h[(size_t)NN * WW];        // relu(layer1), fp16
__device__ __half g_aggh[(size_t)NN * WW];     // A_norm @ h, fp16

__device__ __forceinline__ unsigned long long ffma2(unsigned long long a,
                                                    unsigned long long b,
                                                    unsigned long long c) {
    unsigned long long d;
    asm("fma.rn.f32x2 %0, %1, %2, %3;" : "=l"(d) : "l"(a), "l"(b), "l"(c));
    return d;
}

// ---------------- graph prep ----------------
// g_cnt/g_cur are zero on entry: zero-initialized statics on the first call,
// re-zeroed by k_layer1 (after k_fill) on every call -> identical work per call.
__global__ void k_count(const int* __restrict__ ei) {
    int e = blockIdx.x * blockDim.x + threadIdx.x;
    if (e < EE) atomicAdd(&g_cnt[ei[EE + e]], 1);
}

// stage A: per-block sums of c[i] = cnt[i]+1 over 1024-elem ranges
__global__ void k_scanA() {
    __shared__ int sred[256];
    int b = blockIdx.x, t = threadIdx.x;
    int i0 = (b * 256 + t) * 4;
    int s = 0;
    if (i0 < NN) {
        int4 c = *(const int4*)&g_cnt[i0];
        s = c.x + c.y + c.z + c.w + 4;
    }
    sred[t] = s;
    __syncthreads();
#pragma unroll
    for (int off = 128; off > 0; off >>= 1) {
        if (t < off) sred[t] += sred[t + off];
        __syncthreads();
    }
    if (t == 0) g_bsum[b] = sred[0];
}

// stage C: every block redundantly scans the 49 block sums (warp 0, shfl),
// then rescans its 1024-elem range -> g_off + g_dis.
__global__ void k_scanC() {
    __shared__ int ss[256];
    __shared__ int sb[64];
    int b = blockIdx.x, t = threadIdx.x;
    if (t < 32) {
        int v0 = (t < SCB) ? g_bsum[t] : 0;
        int v1 = (t + 32 < SCB) ? g_bsum[t + 32] : 0;
#pragma unroll
        for (int o = 1; o < 32; o <<= 1) {
            int u = __shfl_up_sync(0xffffffffu, v0, o);
            if (t >= o) v0 += u;
        }
        int tot0 = __shfl_sync(0xffffffffu, v0, 31);
#pragma unroll
        for (int o = 1; o < 32; o <<= 1) {
            int u = __shfl_up_sync(0xffffffffu, v1, o);
            if (t >= o) v1 += u;
        }
        sb[t] = v0;
        sb[t + 32] = v1 + tot0;
    }
    __syncthreads();
    int bpre = (b == 0) ? 0 : sb[b - 1];
    if (b == SCB - 1 && t == 0) g_off[NN] = sb[SCB - 1];

    int i0 = (b * 256 + t) * 4;
    int4 c = {0, 0, 0, 0};
    int s = 0;
    if (i0 < NN) {
        c = *(const int4*)&g_cnt[i0];
        c.x += 1; c.y += 1; c.z += 1; c.w += 1;
        s = c.x + c.y + c.z + c.w;
    }
    ss[t] = s;
    __syncthreads();
#pragma unroll
    for (int off = 1; off < 256; off <<= 1) {
        int u = (t >= off) ? ss[t - off] : 0;
        __syncthreads();
        ss[t] += u;
        __syncthreads();
    }
    int run = ss[t] - s + bpre;
    if (i0 < NN) {
        g_off[i0]     = run; g_dis[i0]     = rsqrtf((float)c.x); run += c.x;
        g_off[i0 + 1] = run; g_dis[i0 + 1] = rsqrtf((float)c.y); run += c.y;
        g_off[i0 + 2] = run; g_dis[i0 + 2] = rsqrtf((float)c.z); run += c.z;
        g_off[i0 + 3] = run; g_dis[i0 + 3] = rsqrtf((float)c.w);
    }
}

// fill CSR with packed (src, norm): norm = dis[src]*dis[dst], computed ONCE here
__global__ void k_fill(const int* __restrict__ ei) {
    int i = blockIdx.x * blockDim.x + threadIdx.x;
    if (i < EE) {
        int s = ei[i];
        int d = ei[EE + i];
        float nw = g_dis[s] * g_dis[d];
        int pos = g_off[d] + atomicAdd(&g_cur[d], 1);
        g_edge[pos] = make_int2(s, __float_as_int(nw));
    } else if (i < EE + NN) {
        int n = i - EE;
        float ds = g_dis[n];
        g_edge[g_off[n + 1] - 1] = make_int2(n, __float_as_int(ds * ds));
    }
}

// ------- fused layer 1: 16 nodes/block -------
// phase 1: 8 warps gather 2 nodes each (A_norm @ x, 16-wide) into smem
// phase 2: thread t = fused output col; W1 amortized over 16 nodes
// also: re-zero g_cnt/g_cur for the next call (k_fill is done with them)
__global__ void __launch_bounds__(256) k_layer1(const float* __restrict__ x,
                                                const float* __restrict__ Wc1,
                                                const float* __restrict__ Wv1,
                                                const float* __restrict__ bc1,
                                                const float* __restrict__ bv1) {
    __shared__ float xs[16][IND];
    int t = threadIdx.x, w = t >> 5, lane = t & 31;
    int node0 = blockIdx.x * 16;

    // counter cleanup for next call (grid covers 100k ints)
    int gid = blockIdx.x * 256 + t;
    if (gid < NN) { g_cnt[gid] = 0; g_cur[gid] = 0; }
    else if (gid < NN + 16) g_cnt[gid] = 0;

    int col = lane & 15, slot = lane >> 4;
#pragma unroll
    for (int q = 0; q < 2; q++) {
        int node = node0 + w * 2 + q;
        if (node < NN) {
            int jb = g_off[node], je = g_off[node + 1];
            float acc = 0.f;
            int j = jb + slot;
            for (; j + 2 < je; j += 4) {
                int2 e0 = g_edge[j], e1 = g_edge[j + 2];
                acc = fmaf(__int_as_float(e0.y), x[e0.x * IND + col], acc);
                acc = fmaf(__int_as_float(e1.y), x[e1.x * IND + col], acc);
            }
            for (; j < je; j += 2) {
                int2 e = g_edge[j];
                acc = fmaf(__int_as_float(e.y), x[e.x * IND + col], acc);
            }
            acc += __shfl_down_sync(0xffffffffu, acc, 16);
            if (slot == 0) xs[w * 2 + q][col] = acc;
        }
    }
    __syncthreads();

    const float4* wr = (const float4*)((t < HD) ? (Wc1 + t * IND)
                                                : (Wv1 + (t - HD) * IND));
    float4 w0 = __ldg(&wr[0]), w1 = __ldg(&wr[1]);
    float4 w2 = __ldg(&wr[2]), w3 = __ldg(&wr[3]);
    float bias = (t < HD) ? __ldg(&bc1[t]) : __ldg(&bv1[t - HD]);
#pragma unroll
    for (int n = 0; n < 16; n++) {
        int node = node0 + n;
        if (node >= NN) break;
        float a = bias;
        a = fmaf(w0.x, xs[n][0],  a); a = fmaf(w0.y, xs[n][1],  a);
        a = fmaf(w0.z, xs[n][2],  a); a = fmaf(w0.w, xs[n][3],  a);
        a = fmaf(w1.x, xs[n][4],  a); a = fmaf(w1.y, xs[n][5],  a);
        a = fmaf(w1.z, xs[n][6],  a); a = fmaf(w1.w, xs[n][7],  a);
        a = fmaf(w2.x, xs[n][8],  a); a = fmaf(w2.y, xs[n][9],  a);
        a = fmaf(w2.z, xs[n][10], a); a = fmaf(w2.w, xs[n][11], a);
        a = fmaf(w3.x, xs[n][12], a); a = fmaf(w3.y, xs[n][13], a);
        a = fmaf(w3.z, xs[n][14], a); a = fmaf(w3.w, xs[n][15], a);
        g_h[(size_t)node * WW + t] = __float2half(fmaxf(a, 0.f));
    }
}

// ---------------- SpMM on h (256-wide, fp16 gather): aggh = A_norm @ h ------
__device__ __forceinline__ void acc8(float* acc, float nw, uint4 v) {
    float2 p;
    p = __half22float2(*(const __half2*)&v.x);
    acc[0] = fmaf(nw, p.x, acc[0]); acc[1] = fmaf(nw, p.y, acc[1]);
    p = __half22float2(*(((const __half2*)&v.x) + 1));
    acc[2] = fmaf(nw, p.x, acc[2]); acc[3] = fmaf(nw, p.y, acc[3]);
    p = __half22float2(*(const __half2*)&v.z);
    acc[4] = fmaf(nw, p.x, acc[4]); acc[5] = fmaf(nw, p.y, acc[5]);
    p = __half22float2(*(((const __half2*)&v.z) + 1));
    acc[6] = fmaf(nw, p.x, acc[6]); acc[7] = fmaf(nw, p.y, acc[7]);
}

__global__ void __launch_bounds__(256) k_spmmh() {
    int w = threadIdx.x >> 5, lane = threadIdx.x & 31;
    int node = blockIdx.x * 8 + w;
    if (node >= NN) return;
    int jb = g_off[node], je = g_off[node + 1];
    const __half* hp = g_h + (size_t)lane * 8;
    float acc[8];
#pragma unroll
    for (int i = 0; i < 8; i++) acc[i] = 0.f;
    int j = jb;
    for (; j + 4 <= je; j += 4) {
        int2 e0 = g_edge[j],     e1 = g_edge[j + 1];
        int2 e2 = g_edge[j + 2], e3 = g_edge[j + 3];
        uint4 v0 = __ldg((const uint4*)(hp + (size_t)e0.x * WW));
        uint4 v1 = __ldg((const uint4*)(hp + (size_t)e1.x * WW));
        uint4 v2 = __ldg((const uint4*)(hp + (size_t)e2.x * WW));
        uint4 v3 = __ldg((const uint4*)(hp + (size_t)e3.x * WW));
        acc8(acc, __int_as_float(e0.y), v0);
        acc8(acc, __int_as_float(e1.y), v1);
        acc8(acc, __int_as_float(e2.y), v2);
        acc8(acc, __int_as_float(e3.y), v3);
    }
    for (; j < je; j++) {
        int2 e = g_edge[j];
        uint4 v = __ldg((const uint4*)(hp + (size_t)e.x * WW));
        acc8(acc, __int_as_float(e.y), v);
    }
    __half2 ho[4];
#pragma unroll
    for (int i = 0; i < 4; i++)
        ho[i] = __floats2half2_rn(acc[i * 2], acc[i * 2 + 1]);
    *(uint4*)(g_aggh + (size_t)node * WW + lane * 8) = *(uint4*)ho;
}

// ---------------- dense layer 2 + heads ----------------
__global__ void __launch_bounds__(256, 3)
k_gemm2f(const float* __restrict__ Wc2, const float* __restrict__ Wv2,
         const float* __restrict__ bc2, const float* __restrict__ bv2,
         const float* __restrict__ Wp,  const float* __restrict__ Wvh,
         const float* __restrict__ bp,  const float* __restrict__ bvh,
         float* __restrict__ out) {
    __shared__ __align__(16) float hs[WW * GP];   // transposed tile [col][node]
    int t = threadIdx.x;
    int node0 = blockIdx.x * TILE;

#pragma unroll 4
    for (int n = 0; n < TILE; n++) {
        int node = node0 + n;
        hs[t * GP + n] = (node < NN)
            ? __half2float(g_aggh[(size_t)node * WW + t]) : 0.f;
    }
    __syncthreads();

    int kb = t & HD;
    const float4* w4p = (const float4*)((t < HD) ? (Wc2 + t * HD)
                                                 : (Wv2 + (t - HD) * HD));
    unsigned long long acc[16];
#pragma unroll
    for (int i = 0; i < 16; i++) acc[i] = 0ull;

#pragma unroll 1
    for (int k4 = 0; k4 < HD / 4; k4++) {
        float4 wq = __ldg(&w4p[k4]);
#pragma unroll
        for (int sub = 0; sub < 4; sub++) {
            float wk = (sub == 0) ? wq.x : (sub == 1) ? wq.y : (sub == 2) ? wq.z : wq.w;
            unsigned int wb = __float_as_uint(wk);
            unsigned long long w2;
            asm("mov.b64 %0, {%1, %2};" : "=l"(w2) : "r"(wb), "r"(wb));
            const float* row = &hs[(kb + k4 * 4 + sub) * GP];
#pragma unroll
            for (int np = 0; np < 8; np++) {
                ulonglong2 h2 = *(const ulonglong2*)&row[np * 4];
                acc[np * 2]     = ffma2(h2.x, w2, acc[np * 2]);
                acc[np * 2 + 1] = ffma2(h2.y, w2, acc[np * 2 + 1]);
            }
        }
    }
    __syncthreads();

    float bias = (t < HD) ? __ldg(&bc2[t]) : __ldg(&bv2[t - HD]);
    float hw   = (t < HD) ? __ldg(&Wp[t])  : __ldg(&Wvh[t - HD]);
#pragma unroll
    for (int np = 0; np < 16; np++) {
        unsigned int lo, hi;
        asm("mov.b64 {%0, %1}, %2;" : "=r"(lo), "=r"(hi) : "l"(acc[np]));
        hs[t * GP + np * 2]     = fmaxf(__uint_as_float(lo) + bias, 0.f) * hw;
        hs[t * GP + np * 2 + 1] = fmaxf(__uint_as_float(hi) + bias, 0.f) * hw;
    }
    __syncthreads();

    int task = t >> 2, l4 = t & 3;
    int n = task & 31, half = task >> 5;
    float s = 0.f;
#pragma unroll
    for (int i = 0; i < 32; i++) {
        int c = half * HD + l4 * 32 + i;
        s += hs[c * GP + n];
    }
    s += __shfl_down_sync(0xffffffffu, s, 1);
    s += __shfl_down_sync(0xffffffffu, s, 2);
    int node = node0 + n;
    if (l4 == 0 && node < NN) {
        if (half == 0) out[node]      = s + __ldg(&bp[0]);
        else           out[NN + node] = s + __ldg(&bvh[0]);
    }
}

// ---------------- launch (kernel launches ONLY) ----------------
extern "C" void kernel_launch(void* const* d_in, const int* in_sizes, int n_in,
                              void* d_out, int out_size) {
    const float* x   = (const float*)d_in[0];
    const int*   ei  = (const int*)d_in[1];
    const float* Wc1 = (const float*)d_in[2];
    const float* bc1 = (const float*)d_in[3];
    const float* Wc2 = (const float*)d_in[4];
    const float* bc2 = (const float*)d_in[5];
    const float* Wp  = (const float*)d_in[6];
    const float* bp  = (const float*)d_in[7];
    const float* Wv1 = (const float*)d_in[8];
    const float* bv1 = (const float*)d_in[9];
    const float* Wv2 = (const float*)d_in[10];
    const float* bv2 = (const float*)d_in[11];
    const float* Wvh = (const float*)d_in[12];
    const float* bvh = (const float*)d_in[13];
    float* out = (float*)d_out;

    k_count <<<(EE + 255) / 256, 256>>>(ei);
    k_scanA <<<SCB, 256>>>();
    k_scanC <<<SCB, 256>>>();
    k_fill  <<<(EE + NN + 255) / 256, 256>>>(ei);

    k_layer1<<<(NN + 15) / 16, 256>>>(x, Wc1, Wv1, bc1, bv1);
    k_spmmh <<<(NN + 7) / 8, 256>>>();
    k_gemm2f<<<(NN + TILE - 1) / TILE, 256>>>(Wc2, Wv2, bc2, bv2,
                                              Wp, Wvh, bp, bvh, out);
}

// round 11
// speedup vs baseline: 1.7839x; 1.7839x over previous
#include <cuda_runtime.h>
#include <cuda_fp16.h>
#include <mma.h>
#include <cstdint>

using namespace nvcuda;

#define NN 50000
#define EE 800000
#define IND 16
#define HD 128
#define WW 256          // fused width (policy 0..127, value 128..255)
#define SCB 49          // scan blocks
#define ZLD 264         // z/A tile leading dim (elements)

// ---------------- device scratch (static, no allocation; zero-initialized) ----
__device__ int    g_cnt[NN + 16];
__device__ int    g_cur[NN];
__device__ int    g_off[NN + 1];
__device__ int    g_bsum[64];
__device__ int2   g_edge[EE + NN];             // (src, norm-bits) per CSR slot
__device__ float  g_dis[NN];
__device__ __half g_w2h[WW * HD];              // fp16 fused [Wc2;Wv2]
__device__ __half g_h[(size_t)NN * WW];        // relu(layer1), fp16
__device__ __half g_aggh[(size_t)(NN + 32) * WW]; // A_norm @ h, fp16 (+pad rows)

// ---------------- graph prep ----------------
// g_cnt/g_cur zero on entry (zero-init statics; re-zeroed by k_layer1 each call)
__global__ void k_count(const int* __restrict__ ei,
                        const float* __restrict__ Wc2,
                        const float* __restrict__ Wv2) {
    int e = blockIdx.x * blockDim.x + threadIdx.x;
    if (e < EE) atomicAdd(&g_cnt[ei[EE + e]], 1);
    // piggyback: fp16 weight conversion for the tensor-core gemm2
    if (e < WW * HD)
        g_w2h[e] = __float2half((e < HD * HD) ? Wc2[e] : Wv2[e - HD * HD]);
}

// stage A: per-block sums of c[i] = cnt[i]+1 over 1024-elem ranges
__global__ void k_scanA() {
    __shared__ int sred[256];
    int b = blockIdx.x, t = threadIdx.x;
    int i0 = (b * 256 + t) * 4;
    int s = 0;
    if (i0 < NN) {
        int4 c = *(const int4*)&g_cnt[i0];
        s = c.x + c.y + c.z + c.w + 4;
    }
    sred[t] = s;
    __syncthreads();
#pragma unroll
    for (int off = 128; off > 0; off >>= 1) {
        if (t < off) sred[t] += sred[t + off];
        __syncthreads();
    }
    if (t == 0) g_bsum[b] = sred[0];
}

// stage C: every block redundantly scans the 49 block sums, then rescans
__global__ void k_scanC() {
    __shared__ int ss[256];
    __shared__ int sb[64];
    int b = blockIdx.x, t = threadIdx.x;
    if (t < 32) {
        int v0 = (t < SCB) ? g_bsum[t] : 0;
        int v1 = (t + 32 < SCB) ? g_bsum[t + 32] : 0;
#pragma unroll
        for (int o = 1; o < 32; o <<= 1) {
            int u = __shfl_up_sync(0xffffffffu, v0, o);
            if (t >= o) v0 += u;
        }
        int tot0 = __shfl_sync(0xffffffffu, v0, 31);
#pragma unroll
        for (int o = 1; o < 32; o <<= 1) {
            int u = __shfl_up_sync(0xffffffffu, v1, o);
            if (t >= o) v1 += u;
        }
        sb[t] = v0;
        sb[t + 32] = v1 + tot0;
    }
    __syncthreads();
    int bpre = (b == 0) ? 0 : sb[b - 1];
    if (b == SCB - 1 && t == 0) g_off[NN] = sb[SCB - 1];

    int i0 = (b * 256 + t) * 4;
    int4 c = {0, 0, 0, 0};
    int s = 0;
    if (i0 < NN) {
        c = *(const int4*)&g_cnt[i0];
        c.x += 1; c.y += 1; c.z += 1; c.w += 1;
        s = c.x + c.y + c.z + c.w;
    }
    ss[t] = s;
    __syncthreads();
#pragma unroll
    for (int off = 1; off < 256; off <<= 1) {
        int u = (t >= off) ? ss[t - off] : 0;
        __syncthreads();
        ss[t] += u;
        __syncthreads();
    }
    int run = ss[t] - s + bpre;
    if (i0 < NN) {
        g_off[i0]     = run; g_dis[i0]     = rsqrtf((float)c.x); run += c.x;
        g_off[i0 + 1] = run; g_dis[i0 + 1] = rsqrtf((float)c.y); run += c.y;
        g_off[i0 + 2] = run; g_dis[i0 + 2] = rsqrtf((float)c.z); run += c.z;
        g_off[i0 + 3] = run; g_dis[i0 + 3] = rsqrtf((float)c.w);
    }
}

// fill CSR with packed (src, norm)
__global__ void k_fill(const int* __restrict__ ei) {
    int i = blockIdx.x * blockDim.x + threadIdx.x;
    if (i < EE) {
        int s = ei[i];
        int d = ei[EE + i];
        float nw = g_dis[s] * g_dis[d];
        int pos = g_off[d] + atomicAdd(&g_cur[d], 1);
        g_edge[pos] = make_int2(s, __float_as_int(nw));
    } else if (i < EE + NN) {
        int n = i - EE;
        float ds = g_dis[n];
        g_edge[g_off[n + 1] - 1] = make_int2(n, __float_as_int(ds * ds));
    }
}

// ------- fused layer 1: 16 nodes/block (gather x, apply W1, relu -> fp16) -----
__global__ void __launch_bounds__(256) k_layer1(const float* __restrict__ x,
                                                const float* __restrict__ Wc1,
                                                const float* __restrict__ Wv1,
                                                const float* __restrict__ bc1,
                                                const float* __restrict__ bv1) {
    __shared__ float xs[16][IND];
    int t = threadIdx.x, w = t >> 5, lane = t & 31;
    int node0 = blockIdx.x * 16;

    // counter cleanup for next call
    int gid = blockIdx.x * 256 + t;
    if (gid < NN) { g_cnt[gid] = 0; g_cur[gid] = 0; }
    else if (gid < NN + 16) g_cnt[gid] = 0;

    int col = lane & 15, slot = lane >> 4;
#pragma unroll
    for (int q = 0; q < 2; q++) {
        int node = node0 + w * 2 + q;
        if (node < NN) {
            int jb = g_off[node], je = g_off[node + 1];
            float acc = 0.f;
            int j = jb + slot;
            for (; j + 2 < je; j += 4) {
                int2 e0 = g_edge[j], e1 = g_edge[j + 2];
                acc = fmaf(__int_as_float(e0.y), x[e0.x * IND + col], acc);
                acc = fmaf(__int_as_float(e1.y), x[e1.x * IND + col], acc);
            }
            for (; j < je; j += 2) {
                int2 e = g_edge[j];
                acc = fmaf(__int_as_float(e.y), x[e.x * IND + col], acc);
            }
            acc += __shfl_down_sync(0xffffffffu, acc, 16);
            if (slot == 0) xs[w * 2 + q][col] = acc;
        }
    }
    __syncthreads();

    const float4* wr = (const float4*)((t < HD) ? (Wc1 + t * IND)
                                                : (Wv1 + (t - HD) * IND));
    float4 w0 = __ldg(&wr[0]), w1 = __ldg(&wr[1]);
    float4 w2 = __ldg(&wr[2]), w3 = __ldg(&wr[3]);
    float bias = (t < HD) ? __ldg(&bc1[t]) : __ldg(&bv1[t - HD]);
#pragma unroll
    for (int n = 0; n < 16; n++) {
        int node = node0 + n;
        if (node >= NN) break;
        float a = bias;
        a = fmaf(w0.x, xs[n][0],  a); a = fmaf(w0.y, xs[n][1],  a);
        a = fmaf(w0.z, xs[n][2],  a); a = fmaf(w0.w, xs[n][3],  a);
        a = fmaf(w1.x, xs[n][4],  a); a = fmaf(w1.y, xs[n][5],  a);
        a = fmaf(w1.z, xs[n][6],  a); a = fmaf(w1.w, xs[n][7],  a);
        a = fmaf(w2.x, xs[n][8],  a); a = fmaf(w2.y, xs[n][9],  a);
        a = fmaf(w2.z, xs[n][10], a); a = fmaf(w2.w, xs[n][11], a);
        a = fmaf(w3.x, xs[n][12], a); a = fmaf(w3.y, xs[n][13], a);
        a = fmaf(w3.z, xs[n][14], a); a = fmaf(w3.w, xs[n][15], a);
        g_h[(size_t)node * WW + t] = __float2half(fmaxf(a, 0.f));
    }
}

// ---------------- SpMM on h (256-wide, fp16 gather): aggh = A_norm @ h ------
__device__ __forceinline__ void acc8(float* acc, float nw, uint4 v) {
    float2 p;
    p = __half22float2(*(const __half2*)&v.x);
    acc[0] = fmaf(nw, p.x, acc[0]); acc[1] = fmaf(nw, p.y, acc[1]);
    p = __half22float2(*(((const __half2*)&v.x) + 1));
    acc[2] = fmaf(nw, p.x, acc[2]); acc[3] = fmaf(nw, p.y, acc[3]);
    p = __half22float2(*(const __half2*)&v.z);
    acc[4] = fmaf(nw, p.x, acc[4]); acc[5] = fmaf(nw, p.y, acc[5]);
    p = __half22float2(*(((const __half2*)&v.z) + 1));
    acc[6] = fmaf(nw, p.x, acc[6]); acc[7] = fmaf(nw, p.y, acc[7]);
}

__global__ void __launch_bounds__(256) k_spmmh() {
    int w = threadIdx.x >> 5, lane = threadIdx.x & 31;
    int node = blockIdx.x * 8 + w;
    if (node >= NN) return;
    int jb = g_off[node], je = g_off[node + 1];
    const __half* hp = g_h + (size_t)lane * 8;
    float acc[8];
#pragma unroll
    for (int i = 0; i < 8; i++) acc[i] = 0.f;
    int j = jb;
    for (; j + 4 <= je; j += 4) {
        int2 e0 = g_edge[j],     e1 = g_edge[j + 1];
        int2 e2 = g_edge[j + 2], e3 = g_edge[j + 3];
        uint4 v0 = __ldg((const uint4*)(hp + (size_t)e0.x * WW));
        uint4 v1 = __ldg((const uint4*)(hp + (size_t)e1.x * WW));
        uint4 v2 = __ldg((const uint4*)(hp + (size_t)e2.x * WW));
        uint4 v3 = __ldg((const uint4*)(hp + (size_t)e3.x * WW));
        acc8(acc, __int_as_float(e0.y), v0);
        acc8(acc, __int_as_float(e1.y), v1);
        acc8(acc, __int_as_float(e2.y), v2);
        acc8(acc, __int_as_float(e3.y), v3);
    }
    for (; j < je; j++) {
        int2 e = g_edge[j];
        uint4 v = __ldg((const uint4*)(hp + (size_t)e.x * WW));
        acc8(acc, __int_as_float(e.y), v);
    }
    __half2 ho[4];
#pragma unroll
    for (int i = 0; i < 4; i++)
        ho[i] = __floats2half2_rn(acc[i * 2], acc[i * 2 + 1]);
    *(uint4*)(g_aggh + (size_t)node * WW + lane * 8) = *(uint4*)ho;
}

// ---------------- dense layer 2 + heads (tensor cores) ----------------
// 32 nodes/block, 8 warps; warp w owns n-cols [w*32, w*32+32).
// A staged in smem fp16 (reused by all warps), B from global fp16 (L1-resident).
// smem buffer is A tile (fp16) during mainloop, z tile (fp32) in epilogue.
__global__ void __launch_bounds__(256)
k_gemm2t(const float* __restrict__ bc2, const float* __restrict__ bv2,
         const float* __restrict__ Wp,  const float* __restrict__ Wvh,
         const float* __restrict__ bp,  const float* __restrict__ bvh,
         float* __restrict__ out) {
    __shared__ __align__(16) char sbuf[32 * ZLD * 4];   // 33.8 KB
    __half* As = (__half*)sbuf;                         // [32][ZLD] halves
    float*  zs = (float*)sbuf;                          // [32][ZLD] floats
    int t = threadIdx.x, warp = t >> 5;
    int node0 = blockIdx.x * 32;

    // stage A tile: 32 rows x 256 halves = 1024 uint4 (g_aggh is row-padded)
    {
        const uint4* src = (const uint4*)(g_aggh + (size_t)node0 * WW);
        uint4* dst = (uint4*)As;
#pragma unroll
        for (int i = 0; i < 4; i++) {
            int idx = t + i * 256;             // 0..1023
            int m = idx >> 5, c8 = idx & 31;   // 32 uint4 per row
            dst[m * (ZLD / 8) + c8] = src[m * (WW / 8) + c8];
        }
    }
    __syncthreads();

    int nb = warp * 32;                 // output col base
    int kb = (warp < 4) ? 0 : HD;       // A k-offset per branch
    const __half* Bbase = g_w2h + nb * HD;

    wmma::fragment<wmma::accumulator, 16, 16, 16, float> c[2][2];
#pragma unroll
    for (int mi = 0; mi < 2; mi++)
#pragma unroll
        for (int ni = 0; ni < 2; ni++) wmma::fill_fragment(c[mi][ni], 0.f);

#pragma unroll
    for (int k = 0; k < HD; k += 16) {
        wmma::fragment<wmma::matrix_a, 16, 16, 16, __half, wmma::row_major> a0, a1;
        wmma::load_matrix_sync(a0, As + kb + k, ZLD);
        wmma::load_matrix_sync(a1, As + 16 * ZLD + kb + k, ZLD);
        wmma::fragment<wmma::matrix_b, 16, 16, 16, __half, wmma::col_major> b0, b1;
        wmma::load_matrix_sync(b0, Bbase + k, HD);
        wmma::load_matrix_sync(b1, Bbase + 16 * HD + k, HD);
        wmma::mma_sync(c[0][0], a0, b0, c[0][0]);
        wmma::mma_sync(c[0][1], a0, b1, c[0][1]);
        wmma::mma_sync(c[1][0], a1, b0, c[1][0]);
        wmma::mma_sync(c[1][1], a1, b1, c[1][1]);
    }
    __syncthreads();   // done reading As; reuse as zs

#pragma unroll
    for (int mi = 0; mi < 2; mi++)
#pragma unroll
        for (int ni = 0; ni < 2; ni++)
            wmma::store_matrix_sync(zs + (mi * 16) * ZLD + nb + ni * 16,
                                    c[mi][ni], ZLD, wmma::mem_row_major);
    __syncthreads();

    // relu + bias, pre-multiply by head weight (thread t = col t)
    float bias = (t < HD) ? __ldg(&bc2[t]) : __ldg(&bv2[t - HD]);
    float hw   = (t < HD) ? __ldg(&Wp[t])  : __ldg(&Wvh[t - HD]);
#pragma unroll 8
    for (int n = 0; n < 32; n++) {
        float v = zs[n * ZLD + t];
        zs[n * ZLD + t] = fmaxf(v + bias, 0.f) * hw;
    }
    __syncthreads();

    // reduce: 64 tasks (32 nodes x 2 halves), 4 threads each sum 32 cols
    int task = t >> 2, l4 = t & 3;
    int n = task & 31, half = task >> 5;
    const float* row = zs + n * ZLD + half * HD + l4 * 32;
    float s = 0.f;
#pragma unroll
    for (int i = 0; i < 32; i++) s += row[i];
    s += __shfl_down_sync(0xffffffffu, s, 1);
    s += __shfl_down_sync(0xffffffffu, s, 2);
    int node = node0 + n;
    if (l4 == 0 && node < NN) {
        if (half == 0) out[node]      = s + __ldg(&bp[0]);
        else           out[NN + node] = s + __ldg(&bvh[0]);
    }
}

// ---------------- launch (kernel launches ONLY) ----------------
extern "C" void kernel_launch(void* const* d_in, const int* in_sizes, int n_in,
                              void* d_out, int out_size) {
    const float* x   = (const float*)d_in[0];
    const int*   ei  = (const int*)d_in[1];
    const float* Wc1 = (const float*)d_in[2];
    const float* bc1 = (const float*)d_in[3];
    const float* Wc2 = (const float*)d_in[4];
    const float* bc2 = (const float*)d_in[5];
    const float* Wp  = (const float*)d_in[6];
    const float* bp  = (const float*)d_in[7];
    const float* Wv1 = (const float*)d_in[8];
    const float* bv1 = (const float*)d_in[9];
    const float* Wv2 = (const float*)d_in[10];
    const float* bv2 = (const float*)d_in[11];
    const float* Wvh = (const float*)d_in[12];
    const float* bvh = (const float*)d_in[13];
    float* out = (float*)d_out;

    k_count <<<(EE + 255) / 256, 256>>>(ei, Wc2, Wv2);
    k_scanA <<<SCB, 256>>>();
    k_scanC <<<SCB, 256>>>();
    k_fill  <<<(EE + NN + 255) / 256, 256>>>(ei);

    k_layer1<<<(NN + 15) / 16, 256>>>(x, Wc1, Wv1, bc1, bv1);
    k_spmmh <<<(NN + 7) / 8, 256>>>();
    k_gemm2t<<<(NN + 31) / 32, 256>>>(bc2, bv2, Wp, Wvh, bp, bvh, out);
}